// round 8
// baseline (speedup 1.0000x reference)
#include <cuda_runtime.h>
#include <cuda_bf16.h>
#include <stdint.h>
#include <math.h>

#define NN 65536
#define EE 1048576
#define NEG 0.2f
#define EPSV 1e-16f

// ---------------- scratch (device globals: allocation-free) ----------------
__device__ int   g_is64;
__device__ int   g_src[EE];
__device__ int   g_dst[EE];
__device__ int   g_deg[NN];
__device__ int   g_off[NN + 1];
__device__ int   g_cur[NN];
__device__ int   g_csr[EE];
__device__ float g_h1[NN * 128];
__device__ float g_as1[NN * 4];
__device__ float g_ad1[NN * 4];
__device__ float g_out1[NN * 128];
__device__ float g_h2[NN * 64];
__device__ float g_as2[NN];
__device__ float g_ad2[NN];

__device__ __forceinline__ float lrelu(float a) { return a > 0.f ? a : NEG * a; }
__device__ __forceinline__ float sigm(float x) { return 1.f / (1.f + __expf(-x)); }
__device__ __forceinline__ uint32_t pack_bf2(__nv_bfloat16 a, __nv_bfloat16 b) {
    return ((uint32_t)__bfloat16_as_ushort(b) << 16) | (uint32_t)__bfloat16_as_ushort(a);
}
__device__ __forceinline__ uint32_t smem_u32(const void* p) {
    uint32_t a;
    asm("{ .reg .u64 t; cvta.to.shared.u64 t, %1; cvt.u32.u64 %0, t; }" : "=r"(a) : "l"(p));
    return a;
}
__device__ __forceinline__ void ldm_x4(uint32_t* r, uint32_t addr) {
    asm volatile("ldmatrix.sync.aligned.m8n8.x4.shared.b16 {%0,%1,%2,%3}, [%4];"
                 : "=r"(r[0]), "=r"(r[1]), "=r"(r[2]), "=r"(r[3]) : "r"(addr));
}
__device__ __forceinline__ void mma16816(float* c, const uint32_t* a, uint32_t b0, uint32_t b1) {
    asm volatile(
        "mma.sync.aligned.m16n8k16.row.col.f32.bf16.bf16.f32 "
        "{%0,%1,%2,%3}, {%4,%5,%6,%7}, {%8,%9}, {%0,%1,%2,%3};"
        : "+f"(c[0]), "+f"(c[1]), "+f"(c[2]), "+f"(c[3])
        : "r"(a[0]), "r"(a[1]), "r"(a[2]), "r"(a[3]), "r"(b0), "r"(b1));
}

// ---------------- preprocessing ----------------
__global__ void k_zero_detect(const unsigned int* __restrict__ ei) {
    int i = blockIdx.x * blockDim.x + threadIdx.x;
    for (int j = i; j < NN; j += gridDim.x * blockDim.x) g_deg[j] = 0;
    if (blockIdx.x == 0 && threadIdx.x < 32) {
        int lane = threadIdx.x;
        unsigned int nz = 0;
#pragma unroll
        for (int k = 0; k < 4; k++) nz |= ei[2 * (lane * 4 + k) + 1];
        unsigned int any = __ballot_sync(0xffffffffu, nz != 0u);
        if (lane == 0) g_is64 = (any == 0u) ? 1 : 0;
    }
}

__global__ void k_convert(const void* __restrict__ ei) {
    int base = blockIdx.x * 1024 + threadIdx.x;
    int is64 = g_is64;
#pragma unroll
    for (int j = 0; j < 4; j++) {
        int e = base + j * 256;
        int s, d;
        if (is64) {
            const long long* p = (const long long*)ei;
            s = (int)p[e];
            d = (int)p[EE + e];
        } else {
            const int* p = (const int*)ei;
            s = p[e];
            d = p[EE + e];
        }
        g_src[e] = s;
        g_dst[e] = d;
        atomicAdd(&g_deg[d], 1);
    }
}

__global__ void __launch_bounds__(1024) k_scan() {
    __shared__ int part[1024];
    int tid = threadIdx.x;
    const int per = NN / 1024;
    int base = tid * per;
    int s = 0;
    for (int i = 0; i < per; i++) s += g_deg[base + i];
    part[tid] = s;
    __syncthreads();
    for (int off = 1; off < 1024; off <<= 1) {
        int v = (tid >= off) ? part[tid - off] : 0;
        __syncthreads();
        part[tid] += v;
        __syncthreads();
    }
    int run = (tid == 0) ? 0 : part[tid - 1];
    for (int i = 0; i < per; i++) {
        g_off[base + i] = run;
        g_cur[base + i] = run;
        run += g_deg[base + i];
    }
    if (tid == 1023) g_off[NN] = part[1023];
}

__global__ void k_csr() {
    int base = blockIdx.x * 1024 + threadIdx.x;
#pragma unroll
    for (int j = 0; j < 4; j++) {
        int e = base + j * 256;
        int pos = atomicAdd(&g_cur[g_dst[e]], 1);
        g_csr[pos] = g_src[e];
    }
}

// ---------------- fused HMMA GEMM + attention dots (K-chunked, ldmatrix) ----------------
// D[128, NB] = A[128,128] * W[128,NB]; 2 K-chunks of 64; bf16 hi/lo 3-pass per chunk.
template <int NB, int HEADS_T, int HC>
__global__ void __launch_bounds__(256, 2) k_mma(
    const float* __restrict__ A, const float* __restrict__ Wsrc,
    const float* __restrict__ ats, const float* __restrict__ atd,
    float* __restrict__ Hout, float* __restrict__ as_out, float* __restrict__ ad_out) {
    constexpr int PITCH = 72;   // bf16/row: 144B stride == 4 words mod 32 -> ldmatrix conflict-free
    constexpr int NT = NB / 8;
    extern __shared__ __align__(16) char smem[];
    __nv_bfloat16* Ah = (__nv_bfloat16*)smem;
    __nv_bfloat16* Al = Ah + 128 * PITCH;
    __nv_bfloat16* Bh = Al + 128 * PITCH;
    __nv_bfloat16* Bl = Bh + NB * PITCH;
    float* s_as = (float*)(Bl + NB * PITCH);
    float* s_ad = s_as + NB;

    int t = threadIdx.x, w = t >> 5, lane = t & 31;
    int gid = lane >> 2, tid4 = lane & 3;
    int row0 = blockIdx.x * 128;
    int wr = w * 16;

    // ldmatrix lane addressing (same pattern for A and B x4 tiles)
    int lm_r = lane & 15;              // row within 16-row tile
    int lm_k = (lane & 16) >> 1;       // 0 or 8 (k element offset)

    uint32_t uAh = smem_u32(Ah), uAl = smem_u32(Al);
    uint32_t uBh = smem_u32(Bh), uBl = smem_u32(Bl);

    for (int idx = t; idx < NB; idx += 256) {
        s_as[idx] = ats[idx];
        s_ad[idx] = atd[idx];
    }

    float acc[NT][4];
#pragma unroll
    for (int nt = 0; nt < NT; nt++) {
        acc[nt][0] = 0.f; acc[nt][1] = 0.f; acc[nt][2] = 0.f; acc[nt][3] = 0.f;
    }

#pragma unroll
    for (int kc = 0; kc < 2; kc++) {
        if (kc) __syncthreads();  // protect smem from previous chunk's readers
        // ---- A chunk: 128 rows x 64 cols -> hi/lo ----
#pragma unroll
        for (int i = 0; i < 8; i++) {
            int idx = i * 256 + t;
            int r = idx >> 4, c4 = idx & 15;
            float4 v = *(const float4*)&A[(size_t)(row0 + r) * 128 + kc * 64 + c4 * 4];
            __nv_bfloat16 hx = __float2bfloat16(v.x), hy = __float2bfloat16(v.y);
            __nv_bfloat16 hz = __float2bfloat16(v.z), hw = __float2bfloat16(v.w);
            __nv_bfloat16 lx = __float2bfloat16(v.x - __bfloat162float(hx));
            __nv_bfloat16 ly = __float2bfloat16(v.y - __bfloat162float(hy));
            __nv_bfloat16 lz = __float2bfloat16(v.z - __bfloat162float(hz));
            __nv_bfloat16 lw = __float2bfloat16(v.w - __bfloat162float(hw));
            int o = r * PITCH + c4 * 4;
            *(uint2*)&Ah[o] = make_uint2(pack_bf2(hx, hy), pack_bf2(hz, hw));
            *(uint2*)&Al[o] = make_uint2(pack_bf2(lx, ly), pack_bf2(lz, lw));
        }
        // ---- B chunk: BT[n][k] = W[kc*64+k][n] -> hi/lo ----
        for (int idx = t; idx < 64 * (NB / 4); idx += 256) {
            int k = idx / (NB / 4), n4 = idx % (NB / 4);
            float4 wv4 = *(const float4*)&Wsrc[(size_t)(kc * 64 + k) * NB + n4 * 4];
            float wv[4] = {wv4.x, wv4.y, wv4.z, wv4.w};
#pragma unroll
            for (int j = 0; j < 4; j++) {
                int n = n4 * 4 + j;
                __nv_bfloat16 h = __float2bfloat16(wv[j]);
                Bh[n * PITCH + k] = h;
                Bl[n * PITCH + k] = __float2bfloat16(wv[j] - __bfloat162float(h));
            }
        }
        __syncthreads();

        // ---- MMA: 4 k-tiles; fragments loaded once, used by all 3 passes ----
#pragma unroll
        for (int kt = 0; kt < 4; kt++) {
            uint32_t aoff = (uint32_t)(((wr + lm_r) * PITCH + kt * 16 + lm_k) * 2);
            uint32_t ah[4], al[4];
            ldm_x4(ah, uAh + aoff);
            ldm_x4(al, uAl + aoff);
#pragma unroll
            for (int np = 0; np < NT / 2; np++) {
                uint32_t boff = (uint32_t)(((np * 16 + lm_r) * PITCH + kt * 16 + lm_k) * 2);
                uint32_t bh[4], bl[4];
                ldm_x4(bh, uBh + boff);
                ldm_x4(bl, uBl + boff);
                // pass ah*bh
                mma16816(acc[np * 2],     ah, bh[0], bh[2]);
                mma16816(acc[np * 2 + 1], ah, bh[1], bh[3]);
                // pass ah*bl
                mma16816(acc[np * 2],     ah, bl[0], bl[2]);
                mma16816(acc[np * 2 + 1], ah, bl[1], bl[3]);
                // pass al*bh
                mma16816(acc[np * 2],     al, bh[0], bh[2]);
                mma16816(acc[np * 2 + 1], al, bh[1], bh[3]);
            }
        }
    }

    // ---- epilogue: H rows + fused attention dots ----
    float accs[2][HEADS_T], accd[2][HEADS_T];
#pragma unroll
    for (int i = 0; i < 2; i++)
#pragma unroll
        for (int h = 0; h < HEADS_T; h++) { accs[i][h] = 0.f; accd[i][h] = 0.f; }

    int gr1 = row0 + wr + gid, gr2 = gr1 + 8;
#pragma unroll
    for (int nt = 0; nt < NT; nt++) {
        const int hidx = (nt * 8) / HC;
        int c0 = nt * 8 + tid4 * 2;
        float as0 = s_as[c0], as1 = s_as[c0 + 1];
        float ad0 = s_ad[c0], ad1 = s_ad[c0 + 1];
        accs[0][hidx] += acc[nt][0] * as0 + acc[nt][1] * as1;
        accd[0][hidx] += acc[nt][0] * ad0 + acc[nt][1] * ad1;
        accs[1][hidx] += acc[nt][2] * as0 + acc[nt][3] * as1;
        accd[1][hidx] += acc[nt][2] * ad0 + acc[nt][3] * ad1;
        *(float2*)&Hout[(size_t)gr1 * NB + c0] = make_float2(acc[nt][0], acc[nt][1]);
        *(float2*)&Hout[(size_t)gr2 * NB + c0] = make_float2(acc[nt][2], acc[nt][3]);
    }
#pragma unroll
    for (int off = 1; off <= 2; off <<= 1) {
#pragma unroll
        for (int i = 0; i < 2; i++)
#pragma unroll
            for (int h = 0; h < HEADS_T; h++) {
                accs[i][h] += __shfl_xor_sync(0xffffffffu, accs[i][h], off);
                accd[i][h] += __shfl_xor_sync(0xffffffffu, accd[i][h], off);
            }
    }
    if (tid4 == 0) {
#pragma unroll
        for (int h = 0; h < HEADS_T; h++) {
            as_out[(size_t)gr1 * HEADS_T + h] = accs[0][h];
            ad_out[(size_t)gr1 * HEADS_T + h] = accd[0][h];
            as_out[(size_t)gr2 * HEADS_T + h] = accs[1][h];
            ad_out[(size_t)gr2 * HEADS_T + h] = accd[1][h];
        }
    }
}

// ---------------- layer-1 aggregation: single unnormalized pass ----------------
__global__ void k_agg1(const float* __restrict__ h, const float* __restrict__ b,
                       float* __restrict__ out) {
    int n = (blockIdx.x * blockDim.x + threadIdx.x) >> 5;
    int lane = threadIdx.x & 31;
    if (n >= NN) return;
    int beg = g_off[n], end = g_off[n + 1];
    float4 ad = *(const float4*)&g_ad1[n * 4];

    float a0 = 0.f, a1 = 0.f, a2 = 0.f, a3 = 0.f;
    float d0 = 0.f, d1 = 0.f, d2 = 0.f, d3 = 0.f;

    for (int e0 = beg; e0 < end; e0 += 32) {
        int cnt = min(32, end - e0);
        int s = 0;
        float w0 = 0.f, w1 = 0.f, w2 = 0.f, w3 = 0.f;
        if (lane < cnt) {
            s = g_csr[e0 + lane];
            float4 as = *(const float4*)&g_as1[s * 4];
            w0 = __expf(lrelu(as.x + ad.x));
            w1 = __expf(lrelu(as.y + ad.y));
            w2 = __expf(lrelu(as.z + ad.z));
            w3 = __expf(lrelu(as.w + ad.w));
            d0 += w0; d1 += w1; d2 += w2; d3 += w3;
        }
        for (int j = 0; j < cnt; j++) {
            int sj = __shfl_sync(0xffffffffu, s, j);
            float u0 = __shfl_sync(0xffffffffu, w0, j);
            float u1 = __shfl_sync(0xffffffffu, w1, j);
            float u2 = __shfl_sync(0xffffffffu, w2, j);
            float u3 = __shfl_sync(0xffffffffu, w3, j);
            const float* hp = h + (size_t)sj * 128;
            a0 += u0 * hp[lane];
            a1 += u1 * hp[32 + lane];
            a2 += u2 * hp[64 + lane];
            a3 += u3 * hp[96 + lane];
        }
    }
#pragma unroll
    for (int off = 16; off > 0; off >>= 1) {
        d0 += __shfl_xor_sync(0xffffffffu, d0, off);
        d1 += __shfl_xor_sync(0xffffffffu, d1, off);
        d2 += __shfl_xor_sync(0xffffffffu, d2, off);
        d3 += __shfl_xor_sync(0xffffffffu, d3, off);
    }
    float r0 = 1.f / (d0 + EPSV), r1 = 1.f / (d1 + EPSV);
    float r2 = 1.f / (d2 + EPSV), r3 = 1.f / (d3 + EPSV);
    out[(size_t)n * 128 + lane]      = sigm(a0 * r0 + b[lane]);
    out[(size_t)n * 128 + 32 + lane] = sigm(a1 * r1 + b[32 + lane]);
    out[(size_t)n * 128 + 64 + lane] = sigm(a2 * r2 + b[64 + lane]);
    out[(size_t)n * 128 + 96 + lane] = sigm(a3 * r3 + b[96 + lane]);
}

// ---------------- layer-2 aggregation (heads=1, C=64) ----------------
__global__ void k_agg2(const float* __restrict__ h, const float* __restrict__ b,
                       float* __restrict__ out) {
    int n = (blockIdx.x * blockDim.x + threadIdx.x) >> 5;
    int lane = threadIdx.x & 31;
    if (n >= NN) return;
    int beg = g_off[n], end = g_off[n + 1];
    float ad = g_ad2[n];

    float a0 = 0.f, a1 = 0.f, d = 0.f;
    for (int e0 = beg; e0 < end; e0 += 32) {
        int cnt = min(32, end - e0);
        int s = 0;
        float w = 0.f;
        if (lane < cnt) {
            s = g_csr[e0 + lane];
            w = __expf(lrelu(g_as2[s] + ad));
            d += w;
        }
        for (int j = 0; j < cnt; j++) {
            int sj = __shfl_sync(0xffffffffu, s, j);
            float u = __shfl_sync(0xffffffffu, w, j);
            const float* hp = h + (size_t)sj * 64;
            a0 += u * hp[lane];
            a1 += u * hp[32 + lane];
        }
    }
#pragma unroll
    for (int off = 16; off > 0; off >>= 1)
        d += __shfl_xor_sync(0xffffffffu, d, off);
    float r = 1.f / (d + EPSV);
    out[(size_t)n * 64 + lane]      = sigm(a0 * r + b[lane]);
    out[(size_t)n * 64 + 32 + lane] = sigm(a1 * r + b[32 + lane]);
}

// ---------------- launch ----------------
extern "C" void kernel_launch(void* const* d_in, const int* in_sizes, int n_in,
                              void* d_out, int out_size) {
    const float* x     = (const float*)d_in[0];
    const void*  ei    = d_in[1];
    const float* W1    = (const float*)d_in[2];
    const float* at_s1 = (const float*)d_in[3];
    const float* at_d1 = (const float*)d_in[4];
    const float* b1    = (const float*)d_in[5];
    const float* W2    = (const float*)d_in[6];
    const float* at_s2 = (const float*)d_in[7];
    const float* at_d2 = (const float*)d_in[8];
    const float* b2    = (const float*)d_in[9];
    float* out = (float*)d_out;

    float *h1p, *out1p, *h2p, *as1p, *ad1p, *as2p, *ad2p;
    cudaGetSymbolAddress((void**)&h1p, g_h1);
    cudaGetSymbolAddress((void**)&out1p, g_out1);
    cudaGetSymbolAddress((void**)&h2p, g_h2);
    cudaGetSymbolAddress((void**)&as1p, g_as1);
    cudaGetSymbolAddress((void**)&ad1p, g_ad1);
    cudaGetSymbolAddress((void**)&as2p, g_as2);
    cudaGetSymbolAddress((void**)&ad2p, g_ad2);

    // smem: (A hi+lo)=2*128*72*2, (B hi+lo)=2*NB*72*2, att = 2*NB*4
    const int SM1 = 4 * 128 * 72 * 2 + 2 * 128 * 4;  // 74752
    const int SM2 = 2 * 128 * 72 * 2 + 2 * 64 * 72 * 2 + 2 * 64 * 4;  // 55808
    cudaFuncSetAttribute(k_mma<128, 4, 32>, cudaFuncAttributeMaxDynamicSharedMemorySize, SM1);
    cudaFuncSetAttribute(k_mma<64, 1, 64>, cudaFuncAttributeMaxDynamicSharedMemorySize, SM2);

    // mma1 kept at launch index 3 for the ncu -s5-c1 capture window.
    k_zero_detect<<<256, 256>>>((const unsigned int*)ei);               // 0
    k_convert<<<EE / 1024, 256>>>(ei);                                  // 1
    k_scan<<<1, 1024>>>();                                              // 2
    k_mma<128, 4, 32><<<NN / 128, 256, SM1>>>(x, W1, at_s1, at_d1,      // 3
                                              h1p, as1p, ad1p);
    k_csr<<<EE / 1024, 256>>>();                                        // 4
    k_agg1<<<NN / 8, 256>>>(h1p, b1, out1p);                            // 5

    k_mma<64, 1, 64><<<NN / 128, 256, SM2>>>(out1p, W2, at_s2, at_d2,   // 6
                                             h2p, as2p, ad2p);
    k_agg2<<<NN / 8, 256>>>(h2p, b2, out);                              // 7
}

// round 9
// speedup vs baseline: 1.5541x; 1.5541x over previous
#include <cuda_runtime.h>
#include <cuda_bf16.h>
#include <stdint.h>
#include <math.h>

#define NN 65536
#define EE 1048576
#define NEG 0.2f
#define EPSV 1e-16f

// ---------------- scratch (device globals: allocation-free) ----------------
__device__ int   g_is64;
__device__ int   g_src[EE];
__device__ int   g_dst[EE];
__device__ int   g_deg[NN];
__device__ int   g_off[NN + 1];
__device__ int   g_cur[NN];
__device__ int   g_csr[EE];
__device__ float g_h1[NN * 128];
__device__ float g_as1[NN * 4];
__device__ float g_ad1[NN * 4];
__device__ float g_out1[NN * 128];
__device__ float g_h2[NN * 64];
__device__ float g_as2[NN];
__device__ float g_ad2[NN];

__device__ __forceinline__ float lrelu(float a) { return a > 0.f ? a : NEG * a; }
__device__ __forceinline__ float sigm(float x) { return 1.f / (1.f + __expf(-x)); }
__device__ __forceinline__ uint32_t pack_bf2(__nv_bfloat16 a, __nv_bfloat16 b) {
    return ((uint32_t)__bfloat16_as_ushort(b) << 16) | (uint32_t)__bfloat16_as_ushort(a);
}
__device__ __forceinline__ void mma16816(float* c, const uint32_t* a, uint32_t b0, uint32_t b1) {
    asm volatile(
        "mma.sync.aligned.m16n8k16.row.col.f32.bf16.bf16.f32 "
        "{%0,%1,%2,%3}, {%4,%5,%6,%7}, {%8,%9}, {%0,%1,%2,%3};"
        : "+f"(c[0]), "+f"(c[1]), "+f"(c[2]), "+f"(c[3])
        : "r"(a[0]), "r"(a[1]), "r"(a[2]), "r"(a[3]), "r"(b0), "r"(b1));
}

// ---------------- preprocessing ----------------
__global__ void k_zero_detect(const unsigned int* __restrict__ ei) {
    int i = blockIdx.x * blockDim.x + threadIdx.x;
    for (int j = i; j < NN; j += gridDim.x * blockDim.x) g_deg[j] = 0;
    if (blockIdx.x == 0 && threadIdx.x < 32) {
        int lane = threadIdx.x;
        unsigned int nz = 0;
#pragma unroll
        for (int k = 0; k < 4; k++) nz |= ei[2 * (lane * 4 + k) + 1];
        unsigned int any = __ballot_sync(0xffffffffu, nz != 0u);
        if (lane == 0) g_is64 = (any == 0u) ? 1 : 0;
    }
}

__global__ void k_convert(const void* __restrict__ ei) {
    int base = blockIdx.x * 1024 + threadIdx.x;
    int is64 = g_is64;
#pragma unroll
    for (int j = 0; j < 4; j++) {
        int e = base + j * 256;
        int s, d;
        if (is64) {
            const long long* p = (const long long*)ei;
            s = (int)p[e];
            d = (int)p[EE + e];
        } else {
            const int* p = (const int*)ei;
            s = p[e];
            d = p[EE + e];
        }
        g_src[e] = s;
        g_dst[e] = d;
        atomicAdd(&g_deg[d], 1);
    }
}

__global__ void __launch_bounds__(1024) k_scan() {
    __shared__ int part[1024];
    int tid = threadIdx.x;
    const int per = NN / 1024;
    int base = tid * per;
    int s = 0;
    for (int i = 0; i < per; i++) s += g_deg[base + i];
    part[tid] = s;
    __syncthreads();
    for (int off = 1; off < 1024; off <<= 1) {
        int v = (tid >= off) ? part[tid - off] : 0;
        __syncthreads();
        part[tid] += v;
        __syncthreads();
    }
    int run = (tid == 0) ? 0 : part[tid - 1];
    for (int i = 0; i < per; i++) {
        g_off[base + i] = run;
        g_cur[base + i] = run;
        run += g_deg[base + i];
    }
    if (tid == 1023) g_off[NN] = part[1023];
}

__global__ void k_csr() {
    int base = blockIdx.x * 1024 + threadIdx.x;
#pragma unroll
    for (int j = 0; j < 4; j++) {
        int e = base + j * 256;
        int pos = atomicAdd(&g_cur[g_dst[e]], 1);
        g_csr[pos] = g_src[e];
    }
}

// ---------------- fused HMMA GEMM + attention dots ----------------
// K-chunked (2x64), scalar-LDS fragments (round-7 addressing), frags reused across 3 passes.
template <int NB, int HEADS_T, int HC>
__global__ void __launch_bounds__(256, 2) k_mma(
    const float* __restrict__ A, const float* __restrict__ Wsrc,
    const float* __restrict__ ats, const float* __restrict__ atd,
    float* __restrict__ Hout, float* __restrict__ as_out, float* __restrict__ ad_out) {
    constexpr int PITCH = 72;  // 144B row stride: scalar frag loads land on 32 distinct banks
    constexpr int NT = NB / 8;
    extern __shared__ __align__(16) char smem[];
    __nv_bfloat16* Ah = (__nv_bfloat16*)smem;
    __nv_bfloat16* Al = Ah + 128 * PITCH;
    __nv_bfloat16* Bh = Al + 128 * PITCH;
    __nv_bfloat16* Bl = Bh + NB * PITCH;
    float* s_as = (float*)(Bl + NB * PITCH);
    float* s_ad = s_as + NB;

    int t = threadIdx.x, w = t >> 5, lane = t & 31;
    int gid = lane >> 2, tid4 = lane & 3;
    int row0 = blockIdx.x * 128;
    int wr = w * 16;
    int r1 = wr + gid, r2 = r1 + 8;

    for (int idx = t; idx < NB; idx += 256) {
        s_as[idx] = ats[idx];
        s_ad[idx] = atd[idx];
    }

    float acc[NT][4];
#pragma unroll
    for (int nt = 0; nt < NT; nt++) {
        acc[nt][0] = 0.f; acc[nt][1] = 0.f; acc[nt][2] = 0.f; acc[nt][3] = 0.f;
    }

#pragma unroll
    for (int kc = 0; kc < 2; kc++) {
        if (kc) __syncthreads();  // all readers of previous chunk done
        // ---- A chunk: 128 rows x 64 cols -> hi/lo ----
#pragma unroll
        for (int i = 0; i < 8; i++) {
            int idx = i * 256 + t;
            int r = idx >> 4, c4 = idx & 15;
            float4 v = *(const float4*)&A[(size_t)(row0 + r) * 128 + kc * 64 + c4 * 4];
            __nv_bfloat16 hx = __float2bfloat16(v.x), hy = __float2bfloat16(v.y);
            __nv_bfloat16 hz = __float2bfloat16(v.z), hw = __float2bfloat16(v.w);
            __nv_bfloat16 lx = __float2bfloat16(v.x - __bfloat162float(hx));
            __nv_bfloat16 ly = __float2bfloat16(v.y - __bfloat162float(hy));
            __nv_bfloat16 lz = __float2bfloat16(v.z - __bfloat162float(hz));
            __nv_bfloat16 lw = __float2bfloat16(v.w - __bfloat162float(hw));
            int o = r * PITCH + c4 * 4;
            *(uint2*)&Ah[o] = make_uint2(pack_bf2(hx, hy), pack_bf2(hz, hw));
            *(uint2*)&Al[o] = make_uint2(pack_bf2(lx, ly), pack_bf2(lz, lw));
        }
        // ---- B chunk: BT[n][k] = W[kc*64+k][n] -> hi/lo ----
        for (int idx = t; idx < 64 * (NB / 4); idx += 256) {
            int k = idx / (NB / 4), n4 = idx % (NB / 4);
            float4 wv4 = *(const float4*)&Wsrc[(size_t)(kc * 64 + k) * NB + n4 * 4];
            float wv[4] = {wv4.x, wv4.y, wv4.z, wv4.w};
#pragma unroll
            for (int j = 0; j < 4; j++) {
                int n = n4 * 4 + j;
                __nv_bfloat16 h = __float2bfloat16(wv[j]);
                Bh[n * PITCH + k] = h;
                Bl[n * PITCH + k] = __float2bfloat16(wv[j] - __bfloat162float(h));
            }
        }
        __syncthreads();

        // ---- 4 k-tiles per chunk; fragments loaded once, 3 passes from registers ----
#pragma unroll
        for (int kt = 0; kt < 4; kt++) {
            int k0 = kt * 16 + tid4 * 2;
            uint32_t ah[4], al[4];
            ah[0] = *(const uint32_t*)&Ah[r1 * PITCH + k0];
            ah[1] = *(const uint32_t*)&Ah[r2 * PITCH + k0];
            ah[2] = *(const uint32_t*)&Ah[r1 * PITCH + k0 + 8];
            ah[3] = *(const uint32_t*)&Ah[r2 * PITCH + k0 + 8];
            al[0] = *(const uint32_t*)&Al[r1 * PITCH + k0];
            al[1] = *(const uint32_t*)&Al[r2 * PITCH + k0];
            al[2] = *(const uint32_t*)&Al[r1 * PITCH + k0 + 8];
            al[3] = *(const uint32_t*)&Al[r2 * PITCH + k0 + 8];
#pragma unroll
            for (int nt = 0; nt < NT; nt++) {
                int nr = nt * 8 + gid;
                uint32_t bh0 = *(const uint32_t*)&Bh[nr * PITCH + k0];
                uint32_t bh1 = *(const uint32_t*)&Bh[nr * PITCH + k0 + 8];
                uint32_t bl0 = *(const uint32_t*)&Bl[nr * PITCH + k0];
                uint32_t bl1 = *(const uint32_t*)&Bl[nr * PITCH + k0 + 8];
                mma16816(acc[nt], ah, bh0, bh1);
                mma16816(acc[nt], ah, bl0, bl1);
                mma16816(acc[nt], al, bh0, bh1);
            }
        }
    }

    // ---- epilogue: H rows + fused attention dots ----
    float accs[2][HEADS_T], accd[2][HEADS_T];
#pragma unroll
    for (int i = 0; i < 2; i++)
#pragma unroll
        for (int h = 0; h < HEADS_T; h++) { accs[i][h] = 0.f; accd[i][h] = 0.f; }

    int gr1 = row0 + r1, gr2 = row0 + r2;
#pragma unroll
    for (int nt = 0; nt < NT; nt++) {
        const int hidx = (nt * 8) / HC;
        int c0 = nt * 8 + tid4 * 2;
        float as0 = s_as[c0], as1 = s_as[c0 + 1];
        float ad0 = s_ad[c0], ad1 = s_ad[c0 + 1];
        accs[0][hidx] += acc[nt][0] * as0 + acc[nt][1] * as1;
        accd[0][hidx] += acc[nt][0] * ad0 + acc[nt][1] * ad1;
        accs[1][hidx] += acc[nt][2] * as0 + acc[nt][3] * as1;
        accd[1][hidx] += acc[nt][2] * ad0 + acc[nt][3] * ad1;
        *(float2*)&Hout[(size_t)gr1 * NB + c0] = make_float2(acc[nt][0], acc[nt][1]);
        *(float2*)&Hout[(size_t)gr2 * NB + c0] = make_float2(acc[nt][2], acc[nt][3]);
    }
#pragma unroll
    for (int off = 1; off <= 2; off <<= 1) {
#pragma unroll
        for (int i = 0; i < 2; i++)
#pragma unroll
            for (int h = 0; h < HEADS_T; h++) {
                accs[i][h] += __shfl_xor_sync(0xffffffffu, accs[i][h], off);
                accd[i][h] += __shfl_xor_sync(0xffffffffu, accd[i][h], off);
            }
    }
    if (tid4 == 0) {
#pragma unroll
        for (int h = 0; h < HEADS_T; h++) {
            as_out[(size_t)gr1 * HEADS_T + h] = accs[0][h];
            ad_out[(size_t)gr1 * HEADS_T + h] = accd[0][h];
            as_out[(size_t)gr2 * HEADS_T + h] = accs[1][h];
            ad_out[(size_t)gr2 * HEADS_T + h] = accd[1][h];
        }
    }
}

// ---------------- layer-1 aggregation: single unnormalized pass ----------------
__global__ void k_agg1(const float* __restrict__ h, const float* __restrict__ b,
                       float* __restrict__ out) {
    int n = (blockIdx.x * blockDim.x + threadIdx.x) >> 5;
    int lane = threadIdx.x & 31;
    if (n >= NN) return;
    int beg = g_off[n], end = g_off[n + 1];
    float4 ad = *(const float4*)&g_ad1[n * 4];

    float a0 = 0.f, a1 = 0.f, a2 = 0.f, a3 = 0.f;
    float d0 = 0.f, d1 = 0.f, d2 = 0.f, d3 = 0.f;

    for (int e0 = beg; e0 < end; e0 += 32) {
        int cnt = min(32, end - e0);
        int s = 0;
        float w0 = 0.f, w1 = 0.f, w2 = 0.f, w3 = 0.f;
        if (lane < cnt) {
            s = g_csr[e0 + lane];
            float4 as = *(const float4*)&g_as1[s * 4];
            w0 = __expf(lrelu(as.x + ad.x));
            w1 = __expf(lrelu(as.y + ad.y));
            w2 = __expf(lrelu(as.z + ad.z));
            w3 = __expf(lrelu(as.w + ad.w));
            d0 += w0; d1 += w1; d2 += w2; d3 += w3;
        }
        for (int j = 0; j < cnt; j++) {
            int sj = __shfl_sync(0xffffffffu, s, j);
            float u0 = __shfl_sync(0xffffffffu, w0, j);
            float u1 = __shfl_sync(0xffffffffu, w1, j);
            float u2 = __shfl_sync(0xffffffffu, w2, j);
            float u3 = __shfl_sync(0xffffffffu, w3, j);
            const float* hp = h + (size_t)sj * 128;
            a0 += u0 * hp[lane];
            a1 += u1 * hp[32 + lane];
            a2 += u2 * hp[64 + lane];
            a3 += u3 * hp[96 + lane];
        }
    }
#pragma unroll
    for (int off = 16; off > 0; off >>= 1) {
        d0 += __shfl_xor_sync(0xffffffffu, d0, off);
        d1 += __shfl_xor_sync(0xffffffffu, d1, off);
        d2 += __shfl_xor_sync(0xffffffffu, d2, off);
        d3 += __shfl_xor_sync(0xffffffffu, d3, off);
    }
    float r0 = 1.f / (d0 + EPSV), r1 = 1.f / (d1 + EPSV);
    float r2 = 1.f / (d2 + EPSV), r3 = 1.f / (d3 + EPSV);
    out[(size_t)n * 128 + lane]      = sigm(a0 * r0 + b[lane]);
    out[(size_t)n * 128 + 32 + lane] = sigm(a1 * r1 + b[32 + lane]);
    out[(size_t)n * 128 + 64 + lane] = sigm(a2 * r2 + b[64 + lane]);
    out[(size_t)n * 128 + 96 + lane] = sigm(a3 * r3 + b[96 + lane]);
}

// ---------------- layer-2 aggregation (heads=1, C=64) ----------------
__global__ void k_agg2(const float* __restrict__ h, const float* __restrict__ b,
                       float* __restrict__ out) {
    int n = (blockIdx.x * blockDim.x + threadIdx.x) >> 5;
    int lane = threadIdx.x & 31;
    if (n >= NN) return;
    int beg = g_off[n], end = g_off[n + 1];
    float ad = g_ad2[n];

    float a0 = 0.f, a1 = 0.f, d = 0.f;
    for (int e0 = beg; e0 < end; e0 += 32) {
        int cnt = min(32, end - e0);
        int s = 0;
        float w = 0.f;
        if (lane < cnt) {
            s = g_csr[e0 + lane];
            w = __expf(lrelu(g_as2[s] + ad));
            d += w;
        }
        for (int j = 0; j < cnt; j++) {
            int sj = __shfl_sync(0xffffffffu, s, j);
            float u = __shfl_sync(0xffffffffu, w, j);
            const float* hp = h + (size_t)sj * 64;
            a0 += u * hp[lane];
            a1 += u * hp[32 + lane];
        }
    }
#pragma unroll
    for (int off = 16; off > 0; off >>= 1)
        d += __shfl_xor_sync(0xffffffffu, d, off);
    float r = 1.f / (d + EPSV);
    out[(size_t)n * 64 + lane]      = sigm(a0 * r + b[lane]);
    out[(size_t)n * 64 + 32 + lane] = sigm(a1 * r + b[32 + lane]);
}

// ---------------- launch ----------------
extern "C" void kernel_launch(void* const* d_in, const int* in_sizes, int n_in,
                              void* d_out, int out_size) {
    const float* x     = (const float*)d_in[0];
    const void*  ei    = d_in[1];
    const float* W1    = (const float*)d_in[2];
    const float* at_s1 = (const float*)d_in[3];
    const float* at_d1 = (const float*)d_in[4];
    const float* b1    = (const float*)d_in[5];
    const float* W2    = (const float*)d_in[6];
    const float* at_s2 = (const float*)d_in[7];
    const float* at_d2 = (const float*)d_in[8];
    const float* b2    = (const float*)d_in[9];
    float* out = (float*)d_out;

    float *h1p, *out1p, *h2p, *as1p, *ad1p, *as2p, *ad2p;
    cudaGetSymbolAddress((void**)&h1p, g_h1);
    cudaGetSymbolAddress((void**)&out1p, g_out1);
    cudaGetSymbolAddress((void**)&h2p, g_h2);
    cudaGetSymbolAddress((void**)&as1p, g_as1);
    cudaGetSymbolAddress((void**)&ad1p, g_ad1);
    cudaGetSymbolAddress((void**)&as2p, g_as2);
    cudaGetSymbolAddress((void**)&ad2p, g_ad2);

    // smem per chunk: A hi/lo 2*128*72*2 + B hi/lo 2*NB*72*2 + att 2*NB*4
    const int SM1 = 4 * 128 * 72 * 2 + 2 * 128 * 4;                      // 74752
    const int SM2 = 2 * 128 * 72 * 2 + 2 * 64 * 72 * 2 + 2 * 64 * 4;     // 55808
    cudaFuncSetAttribute(k_mma<128, 4, 32>, cudaFuncAttributeMaxDynamicSharedMemorySize, SM1);
    cudaFuncSetAttribute(k_mma<64, 1, 64>, cudaFuncAttributeMaxDynamicSharedMemorySize, SM2);

    // mma1 kept at launch index 3 for the ncu -s5-c1 capture window.
    k_zero_detect<<<256, 256>>>((const unsigned int*)ei);               // 0
    k_convert<<<EE / 1024, 256>>>(ei);                                  // 1
    k_scan<<<1, 1024>>>();                                              // 2
    k_mma<128, 4, 32><<<NN / 128, 256, SM1>>>(x, W1, at_s1, at_d1,      // 3
                                              h1p, as1p, ad1p);
    k_csr<<<EE / 1024, 256>>>();                                        // 4
    k_agg1<<<NN / 8, 256>>>(h1p, b1, out1p);                            // 5

    k_mma<64, 1, 64><<<NN / 128, 256, SM2>>>(out1p, W2, at_s2, at_d2,   // 6
                                             h2p, as2p, ad2p);
    k_agg2<<<NN / 8, 256>>>(h2p, b2, out);                              // 7
}

// round 10
// speedup vs baseline: 1.6385x; 1.0543x over previous
#include <cuda_runtime.h>
#include <cuda_bf16.h>
#include <stdint.h>
#include <math.h>

#define NN 65536
#define EE 1048576
#define NEG 0.2f
#define EPSV 1e-16f

// ---------------- scratch (device globals: allocation-free) ----------------
__device__ int   g_is64;
__device__ int   g_src[EE];
__device__ int   g_dst[EE];
__device__ int   g_deg[NN];
__device__ int   g_off[NN + 1];
__device__ int   g_cur[NN];
__device__ int   g_csr[EE];
__device__ float g_h1[NN * 128];
__device__ float g_as1[NN * 4];
__device__ float g_ad1[NN * 4];
__device__ float g_out1[NN * 128];
__device__ float g_h2[NN * 64];
__device__ float g_as2[NN];
__device__ float g_ad2[NN];

__device__ __forceinline__ float lrelu(float a) { return a > 0.f ? a : NEG * a; }
__device__ __forceinline__ float sigm(float x) { return 1.f / (1.f + __expf(-x)); }
__device__ __forceinline__ uint32_t pack_bf2(__nv_bfloat16 a, __nv_bfloat16 b) {
    return ((uint32_t)__bfloat16_as_ushort(b) << 16) | (uint32_t)__bfloat16_as_ushort(a);
}
__device__ __forceinline__ void mma16816(float* c, const uint32_t* a, uint32_t b0, uint32_t b1) {
    asm volatile(
        "mma.sync.aligned.m16n8k16.row.col.f32.bf16.bf16.f32 "
        "{%0,%1,%2,%3}, {%4,%5,%6,%7}, {%8,%9}, {%0,%1,%2,%3};"
        : "+f"(c[0]), "+f"(c[1]), "+f"(c[2]), "+f"(c[3])
        : "r"(a[0]), "r"(a[1]), "r"(a[2]), "r"(a[3]), "r"(b0), "r"(b1));
}

// ---------------- preprocessing ----------------
__global__ void k_zero_detect(const unsigned int* __restrict__ ei) {
    int i = blockIdx.x * blockDim.x + threadIdx.x;
    for (int j = i; j < NN; j += gridDim.x * blockDim.x) g_deg[j] = 0;
    if (blockIdx.x == 0 && threadIdx.x < 32) {
        int lane = threadIdx.x;
        unsigned int nz = 0;
#pragma unroll
        for (int k = 0; k < 4; k++) nz |= ei[2 * (lane * 4 + k) + 1];
        unsigned int any = __ballot_sync(0xffffffffu, nz != 0u);
        if (lane == 0) g_is64 = (any == 0u) ? 1 : 0;
    }
}

__global__ void k_convert(const void* __restrict__ ei) {
    int base = blockIdx.x * 1024 + threadIdx.x;
    int is64 = g_is64;
#pragma unroll
    for (int j = 0; j < 4; j++) {
        int e = base + j * 256;
        int s, d;
        if (is64) {
            const long long* p = (const long long*)ei;
            s = (int)p[e];
            d = (int)p[EE + e];
        } else {
            const int* p = (const int*)ei;
            s = p[e];
            d = p[EE + e];
        }
        g_src[e] = s;
        g_dst[e] = d;
        atomicAdd(&g_deg[d], 1);
    }
}

__global__ void __launch_bounds__(1024) k_scan() {
    __shared__ int part[1024];
    int tid = threadIdx.x;
    const int per = NN / 1024;
    int base = tid * per;
    int s = 0;
    for (int i = 0; i < per; i++) s += g_deg[base + i];
    part[tid] = s;
    __syncthreads();
    for (int off = 1; off < 1024; off <<= 1) {
        int v = (tid >= off) ? part[tid - off] : 0;
        __syncthreads();
        part[tid] += v;
        __syncthreads();
    }
    int run = (tid == 0) ? 0 : part[tid - 1];
    for (int i = 0; i < per; i++) {
        g_off[base + i] = run;
        g_cur[base + i] = run;
        run += g_deg[base + i];
    }
    if (tid == 1023) g_off[NN] = part[1023];
}

__global__ void k_csr() {
    int base = blockIdx.x * 1024 + threadIdx.x;
#pragma unroll
    for (int j = 0; j < 4; j++) {
        int e = base + j * 256;
        int pos = atomicAdd(&g_cur[g_dst[e]], 1);
        g_csr[pos] = g_src[e];
    }
}

// ---------------- fused HMMA GEMM + attention dots ----------------
// K-chunked (2x64). A: row-major pitch-72 bf16 hi/lo. B: pair-packed K-major
// BP[k2][n] = uint32{W[2k2][n], W[2k2+1][n]} (= the mma b-frag register format),
// conflict-free STS.128 writes + conflict-free 32-bit reads (pitch 8 mod 32 words).
template <int NB, int HEADS_T, int HC>
__global__ void __launch_bounds__(256, 2) k_mma(
    const float* __restrict__ A, const float* __restrict__ Wsrc,
    const float* __restrict__ ats, const float* __restrict__ atd,
    float* __restrict__ Hout, float* __restrict__ as_out, float* __restrict__ ad_out) {
    constexpr int PITCH = 72;                       // A: bf16 elems/row
    constexpr int BPW = (NB == 128) ? 136 : 72;     // B: uint32 words/row (== 8 mod 32)
    constexpr int NT = NB / 8;
    extern __shared__ __align__(16) char smem[];
    __nv_bfloat16* Ah = (__nv_bfloat16*)smem;
    __nv_bfloat16* Al = Ah + 128 * PITCH;
    uint32_t* BPh = (uint32_t*)(Al + 128 * PITCH);
    uint32_t* BPl = BPh + 32 * BPW;
    float* s_as = (float*)(BPl + 32 * BPW);
    float* s_ad = s_as + NB;

    int t = threadIdx.x, w = t >> 5, lane = t & 31;
    int gid = lane >> 2, tid4 = lane & 3;
    int row0 = blockIdx.x * 128;
    int wr = w * 16;
    int r1 = wr + gid, r2 = r1 + 8;

    for (int idx = t; idx < NB; idx += 256) {
        s_as[idx] = ats[idx];
        s_ad[idx] = atd[idx];
    }

    float acc[NT][4];
#pragma unroll
    for (int nt = 0; nt < NT; nt++) {
        acc[nt][0] = 0.f; acc[nt][1] = 0.f; acc[nt][2] = 0.f; acc[nt][3] = 0.f;
    }

#pragma unroll
    for (int kc = 0; kc < 2; kc++) {
        if (kc) __syncthreads();  // all readers of previous chunk done
        // ---- A chunk: 128 rows x 64 cols -> hi/lo ----
#pragma unroll
        for (int i = 0; i < 8; i++) {
            int idx = i * 256 + t;
            int r = idx >> 4, c4 = idx & 15;
            float4 v = *(const float4*)&A[(size_t)(row0 + r) * 128 + kc * 64 + c4 * 4];
            __nv_bfloat16 hx = __float2bfloat16(v.x), hy = __float2bfloat16(v.y);
            __nv_bfloat16 hz = __float2bfloat16(v.z), hw = __float2bfloat16(v.w);
            __nv_bfloat16 lx = __float2bfloat16(v.x - __bfloat162float(hx));
            __nv_bfloat16 ly = __float2bfloat16(v.y - __bfloat162float(hy));
            __nv_bfloat16 lz = __float2bfloat16(v.z - __bfloat162float(hz));
            __nv_bfloat16 lw = __float2bfloat16(v.w - __bfloat162float(hw));
            int o = r * PITCH + c4 * 4;
            *(uint2*)&Ah[o] = make_uint2(pack_bf2(hx, hy), pack_bf2(hz, hw));
            *(uint2*)&Al[o] = make_uint2(pack_bf2(lx, ly), pack_bf2(lz, lw));
        }
        // ---- B chunk: pair-packed, BP[k2][n] covers W rows 2k2, 2k2+1 ----
#pragma unroll
        for (int idx = t; idx < 32 * (NB / 4); idx += 256) {
            int k2 = idx / (NB / 4), n4 = idx % (NB / 4);
            const float* wr0 = &Wsrc[(size_t)(kc * 64 + 2 * k2) * NB + n4 * 4];
            float4 w0 = *(const float4*)wr0;
            float4 w1 = *(const float4*)(wr0 + NB);
            float f0[4] = {w0.x, w0.y, w0.z, w0.w};
            float f1[4] = {w1.x, w1.y, w1.z, w1.w};
            uint32_t ph[4], pl[4];
#pragma unroll
            for (int j = 0; j < 4; j++) {
                __nv_bfloat16 h0 = __float2bfloat16(f0[j]);
                __nv_bfloat16 h1 = __float2bfloat16(f1[j]);
                __nv_bfloat16 l0 = __float2bfloat16(f0[j] - __bfloat162float(h0));
                __nv_bfloat16 l1 = __float2bfloat16(f1[j] - __bfloat162float(h1));
                ph[j] = pack_bf2(h0, h1);
                pl[j] = pack_bf2(l0, l1);
            }
            *(uint4*)&BPh[k2 * BPW + n4 * 4] = make_uint4(ph[0], ph[1], ph[2], ph[3]);
            *(uint4*)&BPl[k2 * BPW + n4 * 4] = make_uint4(pl[0], pl[1], pl[2], pl[3]);
        }
        __syncthreads();

        // ---- 4 k-tiles per chunk; fragments loaded once, 3 passes from registers ----
#pragma unroll
        for (int kt = 0; kt < 4; kt++) {
            int k0 = kt * 16 + tid4 * 2;
            int p0 = kt * 8 + tid4;  // k-pair row in BP
            uint32_t ah[4], al[4];
            ah[0] = *(const uint32_t*)&Ah[r1 * PITCH + k0];
            ah[1] = *(const uint32_t*)&Ah[r2 * PITCH + k0];
            ah[2] = *(const uint32_t*)&Ah[r1 * PITCH + k0 + 8];
            ah[3] = *(const uint32_t*)&Ah[r2 * PITCH + k0 + 8];
            al[0] = *(const uint32_t*)&Al[r1 * PITCH + k0];
            al[1] = *(const uint32_t*)&Al[r2 * PITCH + k0];
            al[2] = *(const uint32_t*)&Al[r1 * PITCH + k0 + 8];
            al[3] = *(const uint32_t*)&Al[r2 * PITCH + k0 + 8];
#pragma unroll
            for (int nt = 0; nt < NT; nt++) {
                int nr = nt * 8 + gid;
                uint32_t bh0 = BPh[p0 * BPW + nr];
                uint32_t bh1 = BPh[(p0 + 4) * BPW + nr];
                uint32_t bl0 = BPl[p0 * BPW + nr];
                uint32_t bl1 = BPl[(p0 + 4) * BPW + nr];
                mma16816(acc[nt], ah, bh0, bh1);
                mma16816(acc[nt], ah, bl0, bl1);
                mma16816(acc[nt], al, bh0, bh1);
            }
        }
    }

    // ---- epilogue: H rows + fused attention dots ----
    float accs[2][HEADS_T], accd[2][HEADS_T];
#pragma unroll
    for (int i = 0; i < 2; i++)
#pragma unroll
        for (int h = 0; h < HEADS_T; h++) { accs[i][h] = 0.f; accd[i][h] = 0.f; }

    int gr1 = row0 + r1, gr2 = row0 + r2;
#pragma unroll
    for (int nt = 0; nt < NT; nt++) {
        const int hidx = (nt * 8) / HC;
        int c0 = nt * 8 + tid4 * 2;
        float as0 = s_as[c0], as1 = s_as[c0 + 1];
        float ad0 = s_ad[c0], ad1 = s_ad[c0 + 1];
        accs[0][hidx] += acc[nt][0] * as0 + acc[nt][1] * as1;
        accd[0][hidx] += acc[nt][0] * ad0 + acc[nt][1] * ad1;
        accs[1][hidx] += acc[nt][2] * as0 + acc[nt][3] * as1;
        accd[1][hidx] += acc[nt][2] * ad0 + acc[nt][3] * ad1;
        *(float2*)&Hout[(size_t)gr1 * NB + c0] = make_float2(acc[nt][0], acc[nt][1]);
        *(float2*)&Hout[(size_t)gr2 * NB + c0] = make_float2(acc[nt][2], acc[nt][3]);
    }
#pragma unroll
    for (int off = 1; off <= 2; off <<= 1) {
#pragma unroll
        for (int i = 0; i < 2; i++)
#pragma unroll
            for (int h = 0; h < HEADS_T; h++) {
                accs[i][h] += __shfl_xor_sync(0xffffffffu, accs[i][h], off);
                accd[i][h] += __shfl_xor_sync(0xffffffffu, accd[i][h], off);
            }
    }
    if (tid4 == 0) {
#pragma unroll
        for (int h = 0; h < HEADS_T; h++) {
            as_out[(size_t)gr1 * HEADS_T + h] = accs[0][h];
            ad_out[(size_t)gr1 * HEADS_T + h] = accd[0][h];
            as_out[(size_t)gr2 * HEADS_T + h] = accs[1][h];
            ad_out[(size_t)gr2 * HEADS_T + h] = accd[1][h];
        }
    }
}

// ---------------- layer-1 aggregation: single unnormalized pass ----------------
__global__ void k_agg1(const float* __restrict__ h, const float* __restrict__ b,
                       float* __restrict__ out) {
    int n = (blockIdx.x * blockDim.x + threadIdx.x) >> 5;
    int lane = threadIdx.x & 31;
    if (n >= NN) return;
    int beg = g_off[n], end = g_off[n + 1];
    float4 ad = *(const float4*)&g_ad1[n * 4];

    float a0 = 0.f, a1 = 0.f, a2 = 0.f, a3 = 0.f;
    float d0 = 0.f, d1 = 0.f, d2 = 0.f, d3 = 0.f;

    for (int e0 = beg; e0 < end; e0 += 32) {
        int cnt = min(32, end - e0);
        int s = 0;
        float w0 = 0.f, w1 = 0.f, w2 = 0.f, w3 = 0.f;
        if (lane < cnt) {
            s = g_csr[e0 + lane];
            float4 as = *(const float4*)&g_as1[s * 4];
            w0 = __expf(lrelu(as.x + ad.x));
            w1 = __expf(lrelu(as.y + ad.y));
            w2 = __expf(lrelu(as.z + ad.z));
            w3 = __expf(lrelu(as.w + ad.w));
            d0 += w0; d1 += w1; d2 += w2; d3 += w3;
        }
        for (int j = 0; j < cnt; j++) {
            int sj = __shfl_sync(0xffffffffu, s, j);
            float u0 = __shfl_sync(0xffffffffu, w0, j);
            float u1 = __shfl_sync(0xffffffffu, w1, j);
            float u2 = __shfl_sync(0xffffffffu, w2, j);
            float u3 = __shfl_sync(0xffffffffu, w3, j);
            const float* hp = h + (size_t)sj * 128;
            a0 += u0 * hp[lane];
            a1 += u1 * hp[32 + lane];
            a2 += u2 * hp[64 + lane];
            a3 += u3 * hp[96 + lane];
        }
    }
#pragma unroll
    for (int off = 16; off > 0; off >>= 1) {
        d0 += __shfl_xor_sync(0xffffffffu, d0, off);
        d1 += __shfl_xor_sync(0xffffffffu, d1, off);
        d2 += __shfl_xor_sync(0xffffffffu, d2, off);
        d3 += __shfl_xor_sync(0xffffffffu, d3, off);
    }
    float r0 = 1.f / (d0 + EPSV), r1 = 1.f / (d1 + EPSV);
    float r2 = 1.f / (d2 + EPSV), r3 = 1.f / (d3 + EPSV);
    out[(size_t)n * 128 + lane]      = sigm(a0 * r0 + b[lane]);
    out[(size_t)n * 128 + 32 + lane] = sigm(a1 * r1 + b[32 + lane]);
    out[(size_t)n * 128 + 64 + lane] = sigm(a2 * r2 + b[64 + lane]);
    out[(size_t)n * 128 + 96 + lane] = sigm(a3 * r3 + b[96 + lane]);
}

// ---------------- layer-2 aggregation (heads=1, C=64) ----------------
__global__ void k_agg2(const float* __restrict__ h, const float* __restrict__ b,
                       float* __restrict__ out) {
    int n = (blockIdx.x * blockDim.x + threadIdx.x) >> 5;
    int lane = threadIdx.x & 31;
    if (n >= NN) return;
    int beg = g_off[n], end = g_off[n + 1];
    float ad = g_ad2[n];

    float a0 = 0.f, a1 = 0.f, d = 0.f;
    for (int e0 = beg; e0 < end; e0 += 32) {
        int cnt = min(32, end - e0);
        int s = 0;
        float w = 0.f;
        if (lane < cnt) {
            s = g_csr[e0 + lane];
            w = __expf(lrelu(g_as2[s] + ad));
            d += w;
        }
        for (int j = 0; j < cnt; j++) {
            int sj = __shfl_sync(0xffffffffu, s, j);
            float u = __shfl_sync(0xffffffffu, w, j);
            const float* hp = h + (size_t)sj * 64;
            a0 += u * hp[lane];
            a1 += u * hp[32 + lane];
        }
    }
#pragma unroll
    for (int off = 16; off > 0; off >>= 1)
        d += __shfl_xor_sync(0xffffffffu, d, off);
    float r = 1.f / (d + EPSV);
    out[(size_t)n * 64 + lane]      = sigm(a0 * r + b[lane]);
    out[(size_t)n * 64 + 32 + lane] = sigm(a1 * r + b[32 + lane]);
}

// ---------------- launch ----------------
extern "C" void kernel_launch(void* const* d_in, const int* in_sizes, int n_in,
                              void* d_out, int out_size) {
    const float* x     = (const float*)d_in[0];
    const void*  ei    = d_in[1];
    const float* W1    = (const float*)d_in[2];
    const float* at_s1 = (const float*)d_in[3];
    const float* at_d1 = (const float*)d_in[4];
    const float* b1    = (const float*)d_in[5];
    const float* W2    = (const float*)d_in[6];
    const float* at_s2 = (const float*)d_in[7];
    const float* at_d2 = (const float*)d_in[8];
    const float* b2    = (const float*)d_in[9];
    float* out = (float*)d_out;

    float *h1p, *out1p, *h2p, *as1p, *ad1p, *as2p, *ad2p;
    cudaGetSymbolAddress((void**)&h1p, g_h1);
    cudaGetSymbolAddress((void**)&out1p, g_out1);
    cudaGetSymbolAddress((void**)&h2p, g_h2);
    cudaGetSymbolAddress((void**)&as1p, g_as1);
    cudaGetSymbolAddress((void**)&ad1p, g_ad1);
    cudaGetSymbolAddress((void**)&as2p, g_as2);
    cudaGetSymbolAddress((void**)&ad2p, g_ad2);

    // smem: A hi/lo 2*128*72*2 + BP hi/lo 2*32*BPW*4 + att 2*NB*4
    const int SM1 = 4 * 128 * 72 * 2 / 2 * 2 + 2 * 32 * 136 * 4 + 2 * 128 * 4;  // 36864+34816+1024 = 72704
    const int SM2 = 2 * 128 * 72 * 2 + 2 * 32 * 72 * 4 + 2 * 64 * 4;            // 36864+18432+512  = 55808
    cudaFuncSetAttribute(k_mma<128, 4, 32>, cudaFuncAttributeMaxDynamicSharedMemorySize, SM1);
    cudaFuncSetAttribute(k_mma<64, 1, 64>, cudaFuncAttributeMaxDynamicSharedMemorySize, SM2);

    // mma1 kept at launch index 3 for the ncu capture window.
    k_zero_detect<<<256, 256>>>((const unsigned int*)ei);               // 0
    k_convert<<<EE / 1024, 256>>>(ei);                                  // 1
    k_scan<<<1, 1024>>>();                                              // 2
    k_mma<128, 4, 32><<<NN / 128, 256, SM1>>>(x, W1, at_s1, at_d1,      // 3
                                              h1p, as1p, ad1p);
    k_csr<<<EE / 1024, 256>>>();                                        // 4
    k_agg1<<<NN / 8, 256>>>(h1p, b1, out1p);                            // 5

    k_mma<64, 1, 64><<<NN / 128, 256, SM2>>>(out1p, W2, at_s2, at_d2,   // 6
                                             h2p, as2p, ad2p);
    k_agg2<<<NN / 8, 256>>>(h2p, b2, out);                              // 7
}

// round 11
// speedup vs baseline: 1.6851x; 1.0285x over previous
#include <cuda_runtime.h>
#include <cuda_bf16.h>
#include <stdint.h>
#include <math.h>

#define NN 65536
#define EE 1048576
#define NEG 0.2f
#define EPSV 1e-16f

// ---------------- scratch (device globals: allocation-free) ----------------
__device__ int   g_is64;
__device__ int   g_src[EE];
__device__ int   g_dst[EE];
__device__ int   g_deg[NN];
__device__ int   g_off[NN + 1];
__device__ int   g_cur[NN];
__device__ int   g_csr[EE];
__device__ float g_h1[NN * 128];
__device__ float g_as1[NN * 4];
__device__ float g_ad1[NN * 4];
__device__ float g_out1[NN * 128];
__device__ float g_h2[NN * 64];
__device__ float g_as2[NN];
__device__ float g_ad2[NN];

__device__ __forceinline__ float lrelu(float a) { return a > 0.f ? a : NEG * a; }
__device__ __forceinline__ float sigm(float x) { return 1.f / (1.f + __expf(-x)); }
__device__ __forceinline__ uint32_t pack_bf2(__nv_bfloat16 a, __nv_bfloat16 b) {
    return ((uint32_t)__bfloat16_as_ushort(b) << 16) | (uint32_t)__bfloat16_as_ushort(a);
}
__device__ __forceinline__ void mma16816(float* c, const uint32_t* a, uint32_t b0, uint32_t b1) {
    asm volatile(
        "mma.sync.aligned.m16n8k16.row.col.f32.bf16.bf16.f32 "
        "{%0,%1,%2,%3}, {%4,%5,%6,%7}, {%8,%9}, {%0,%1,%2,%3};"
        : "+f"(c[0]), "+f"(c[1]), "+f"(c[2]), "+f"(c[3])
        : "r"(a[0]), "r"(a[1]), "r"(a[2]), "r"(a[3]), "r"(b0), "r"(b1));
}

// ---------------- preprocessing ----------------
__global__ void k_zero_detect(const unsigned int* __restrict__ ei) {
    int i = blockIdx.x * blockDim.x + threadIdx.x;
    for (int j = i; j < NN; j += gridDim.x * blockDim.x) g_deg[j] = 0;
    if (blockIdx.x == 0 && threadIdx.x < 32) {
        int lane = threadIdx.x;
        unsigned int nz = 0;
#pragma unroll
        for (int k = 0; k < 4; k++) nz |= ei[2 * (lane * 4 + k) + 1];
        unsigned int any = __ballot_sync(0xffffffffu, nz != 0u);
        if (lane == 0) g_is64 = (any == 0u) ? 1 : 0;
    }
}

__global__ void k_convert(const void* __restrict__ ei) {
    int base = blockIdx.x * 1024 + threadIdx.x;
    int is64 = g_is64;
#pragma unroll
    for (int j = 0; j < 4; j++) {
        int e = base + j * 256;
        int s, d;
        if (is64) {
            const long long* p = (const long long*)ei;
            s = (int)p[e];
            d = (int)p[EE + e];
        } else {
            const int* p = (const int*)ei;
            s = p[e];
            d = p[EE + e];
        }
        g_src[e] = s;
        g_dst[e] = d;
        atomicAdd(&g_deg[d], 1);
    }
}

__global__ void __launch_bounds__(1024) k_scan() {
    __shared__ int part[1024];
    int tid = threadIdx.x;
    const int per = NN / 1024;
    int base = tid * per;
    int s = 0;
    for (int i = 0; i < per; i++) s += g_deg[base + i];
    part[tid] = s;
    __syncthreads();
    for (int off = 1; off < 1024; off <<= 1) {
        int v = (tid >= off) ? part[tid - off] : 0;
        __syncthreads();
        part[tid] += v;
        __syncthreads();
    }
    int run = (tid == 0) ? 0 : part[tid - 1];
    for (int i = 0; i < per; i++) {
        g_off[base + i] = run;
        g_cur[base + i] = run;
        run += g_deg[base + i];
    }
    if (tid == 1023) g_off[NN] = part[1023];
}

__global__ void k_csr() {
    int base = blockIdx.x * 1024 + threadIdx.x;
#pragma unroll
    for (int j = 0; j < 4; j++) {
        int e = base + j * 256;
        int pos = atomicAdd(&g_cur[g_dst[e]], 1);
        g_csr[pos] = g_src[e];
    }
}

// ---------------- fused HMMA GEMM + attention dots ----------------
template <int NB, int HEADS_T, int HC>
__global__ void __launch_bounds__(256, 2) k_mma(
    const float* __restrict__ A, const float* __restrict__ Wsrc,
    const float* __restrict__ ats, const float* __restrict__ atd,
    float* __restrict__ Hout, float* __restrict__ as_out, float* __restrict__ ad_out) {
    constexpr int PITCH = 72;
    constexpr int BPW = (NB == 128) ? 136 : 72;
    constexpr int NT = NB / 8;
    extern __shared__ __align__(16) char smem[];
    __nv_bfloat16* Ah = (__nv_bfloat16*)smem;
    __nv_bfloat16* Al = Ah + 128 * PITCH;
    uint32_t* BPh = (uint32_t*)(Al + 128 * PITCH);
    uint32_t* BPl = BPh + 32 * BPW;
    float* s_as = (float*)(BPl + 32 * BPW);
    float* s_ad = s_as + NB;

    int t = threadIdx.x, w = t >> 5, lane = t & 31;
    int gid = lane >> 2, tid4 = lane & 3;
    int row0 = blockIdx.x * 128;
    int wr = w * 16;
    int r1 = wr + gid, r2 = r1 + 8;

    for (int idx = t; idx < NB; idx += 256) {
        s_as[idx] = ats[idx];
        s_ad[idx] = atd[idx];
    }

    float acc[NT][4];
#pragma unroll
    for (int nt = 0; nt < NT; nt++) {
        acc[nt][0] = 0.f; acc[nt][1] = 0.f; acc[nt][2] = 0.f; acc[nt][3] = 0.f;
    }

#pragma unroll
    for (int kc = 0; kc < 2; kc++) {
        if (kc) __syncthreads();
#pragma unroll
        for (int i = 0; i < 8; i++) {
            int idx = i * 256 + t;
            int r = idx >> 4, c4 = idx & 15;
            float4 v = *(const float4*)&A[(size_t)(row0 + r) * 128 + kc * 64 + c4 * 4];
            __nv_bfloat16 hx = __float2bfloat16(v.x), hy = __float2bfloat16(v.y);
            __nv_bfloat16 hz = __float2bfloat16(v.z), hw = __float2bfloat16(v.w);
            __nv_bfloat16 lx = __float2bfloat16(v.x - __bfloat162float(hx));
            __nv_bfloat16 ly = __float2bfloat16(v.y - __bfloat162float(hy));
            __nv_bfloat16 lz = __float2bfloat16(v.z - __bfloat162float(hz));
            __nv_bfloat16 lw = __float2bfloat16(v.w - __bfloat162float(hw));
            int o = r * PITCH + c4 * 4;
            *(uint2*)&Ah[o] = make_uint2(pack_bf2(hx, hy), pack_bf2(hz, hw));
            *(uint2*)&Al[o] = make_uint2(pack_bf2(lx, ly), pack_bf2(lz, lw));
        }
#pragma unroll
        for (int idx = t; idx < 32 * (NB / 4); idx += 256) {
            int k2 = idx / (NB / 4), n4 = idx % (NB / 4);
            const float* wr0 = &Wsrc[(size_t)(kc * 64 + 2 * k2) * NB + n4 * 4];
            float4 w0 = *(const float4*)wr0;
            float4 w1 = *(const float4*)(wr0 + NB);
            float f0[4] = {w0.x, w0.y, w0.z, w0.w};
            float f1[4] = {w1.x, w1.y, w1.z, w1.w};
            uint32_t ph[4], pl[4];
#pragma unroll
            for (int j = 0; j < 4; j++) {
                __nv_bfloat16 h0 = __float2bfloat16(f0[j]);
                __nv_bfloat16 h1 = __float2bfloat16(f1[j]);
                __nv_bfloat16 l0 = __float2bfloat16(f0[j] - __bfloat162float(h0));
                __nv_bfloat16 l1 = __float2bfloat16(f1[j] - __bfloat162float(h1));
                ph[j] = pack_bf2(h0, h1);
                pl[j] = pack_bf2(l0, l1);
            }
            *(uint4*)&BPh[k2 * BPW + n4 * 4] = make_uint4(ph[0], ph[1], ph[2], ph[3]);
            *(uint4*)&BPl[k2 * BPW + n4 * 4] = make_uint4(pl[0], pl[1], pl[2], pl[3]);
        }
        __syncthreads();

#pragma unroll
        for (int kt = 0; kt < 4; kt++) {
            int k0 = kt * 16 + tid4 * 2;
            int p0 = kt * 8 + tid4;
            uint32_t ah[4], al[4];
            ah[0] = *(const uint32_t*)&Ah[r1 * PITCH + k0];
            ah[1] = *(const uint32_t*)&Ah[r2 * PITCH + k0];
            ah[2] = *(const uint32_t*)&Ah[r1 * PITCH + k0 + 8];
            ah[3] = *(const uint32_t*)&Ah[r2 * PITCH + k0 + 8];
            al[0] = *(const uint32_t*)&Al[r1 * PITCH + k0];
            al[1] = *(const uint32_t*)&Al[r2 * PITCH + k0];
            al[2] = *(const uint32_t*)&Al[r1 * PITCH + k0 + 8];
            al[3] = *(const uint32_t*)&Al[r2 * PITCH + k0 + 8];
#pragma unroll
            for (int nt = 0; nt < NT; nt++) {
                int nr = nt * 8 + gid;
                uint32_t bh0 = BPh[p0 * BPW + nr];
                uint32_t bh1 = BPh[(p0 + 4) * BPW + nr];
                uint32_t bl0 = BPl[p0 * BPW + nr];
                uint32_t bl1 = BPl[(p0 + 4) * BPW + nr];
                mma16816(acc[nt], ah, bh0, bh1);
                mma16816(acc[nt], ah, bl0, bl1);
                mma16816(acc[nt], al, bh0, bh1);
            }
        }
    }

    float accs[2][HEADS_T], accd[2][HEADS_T];
#pragma unroll
    for (int i = 0; i < 2; i++)
#pragma unroll
        for (int h = 0; h < HEADS_T; h++) { accs[i][h] = 0.f; accd[i][h] = 0.f; }

    int gr1 = row0 + r1, gr2 = row0 + r2;
#pragma unroll
    for (int nt = 0; nt < NT; nt++) {
        const int hidx = (nt * 8) / HC;
        int c0 = nt * 8 + tid4 * 2;
        float as0 = s_as[c0], as1 = s_as[c0 + 1];
        float ad0 = s_ad[c0], ad1 = s_ad[c0 + 1];
        accs[0][hidx] += acc[nt][0] * as0 + acc[nt][1] * as1;
        accd[0][hidx] += acc[nt][0] * ad0 + acc[nt][1] * ad1;
        accs[1][hidx] += acc[nt][2] * as0 + acc[nt][3] * as1;
        accd[1][hidx] += acc[nt][2] * ad0 + acc[nt][3] * ad1;
        *(float2*)&Hout[(size_t)gr1 * NB + c0] = make_float2(acc[nt][0], acc[nt][1]);
        *(float2*)&Hout[(size_t)gr2 * NB + c0] = make_float2(acc[nt][2], acc[nt][3]);
    }
#pragma unroll
    for (int off = 1; off <= 2; off <<= 1) {
#pragma unroll
        for (int i = 0; i < 2; i++)
#pragma unroll
            for (int h = 0; h < HEADS_T; h++) {
                accs[i][h] += __shfl_xor_sync(0xffffffffu, accs[i][h], off);
                accd[i][h] += __shfl_xor_sync(0xffffffffu, accd[i][h], off);
            }
    }
    if (tid4 == 0) {
#pragma unroll
        for (int h = 0; h < HEADS_T; h++) {
            as_out[(size_t)gr1 * HEADS_T + h] = accs[0][h];
            ad_out[(size_t)gr1 * HEADS_T + h] = accd[0][h];
            as_out[(size_t)gr2 * HEADS_T + h] = accs[1][h];
            ad_out[(size_t)gr2 * HEADS_T + h] = accd[1][h];
        }
    }
}

// ---------------- layer-1 aggregation: lane-owns-float4, 4x unrolled MLP ----------------
// lane l accumulates channels 4l..4l+3 (head l>>3). One LDG.128 per edge (full row).
__global__ void k_agg1(const float* __restrict__ h, const float* __restrict__ b,
                       float* __restrict__ out) {
    int n = (blockIdx.x * blockDim.x + threadIdx.x) >> 5;
    int lane = threadIdx.x & 31;
    if (n >= NN) return;
    int hsel = lane >> 3;
    int beg = g_off[n], end = g_off[n + 1];
    float4 ad = *(const float4*)&g_ad1[n * 4];

    float4 acc = make_float4(0.f, 0.f, 0.f, 0.f);
    float d0 = 0.f, d1 = 0.f, d2 = 0.f, d3 = 0.f;

    for (int e0 = beg; e0 < end; e0 += 32) {
        int cnt = min(32, end - e0);
        int s = 0;
        float w0 = 0.f, w1 = 0.f, w2 = 0.f, w3 = 0.f;
        if (lane < cnt) {
            s = g_csr[e0 + lane];
            float4 as = *(const float4*)&g_as1[s * 4];
            w0 = __expf(lrelu(as.x + ad.x));
            w1 = __expf(lrelu(as.y + ad.y));
            w2 = __expf(lrelu(as.z + ad.z));
            w3 = __expf(lrelu(as.w + ad.w));
            d0 += w0; d1 += w1; d2 += w2; d3 += w3;
        }
        int j = 0;
        for (; j + 4 <= cnt; j += 4) {
            int sj[4];
            float uq[4];
            float4 v[4];
#pragma unroll
            for (int q = 0; q < 4; q++) {
                int ln = j + q;
                sj[q] = __shfl_sync(0xffffffffu, s, ln);
                float u0 = __shfl_sync(0xffffffffu, w0, ln);
                float u1 = __shfl_sync(0xffffffffu, w1, ln);
                float u2 = __shfl_sync(0xffffffffu, w2, ln);
                float u3 = __shfl_sync(0xffffffffu, w3, ln);
                uq[q] = (hsel < 2) ? (hsel == 0 ? u0 : u1) : (hsel == 2 ? u2 : u3);
            }
#pragma unroll
            for (int q = 0; q < 4; q++)
                v[q] = *(const float4*)&h[(size_t)sj[q] * 128 + lane * 4];
#pragma unroll
            for (int q = 0; q < 4; q++) {
                acc.x += uq[q] * v[q].x;
                acc.y += uq[q] * v[q].y;
                acc.z += uq[q] * v[q].z;
                acc.w += uq[q] * v[q].w;
            }
        }
        for (; j < cnt; j++) {
            int sj = __shfl_sync(0xffffffffu, s, j);
            float u0 = __shfl_sync(0xffffffffu, w0, j);
            float u1 = __shfl_sync(0xffffffffu, w1, j);
            float u2 = __shfl_sync(0xffffffffu, w2, j);
            float u3 = __shfl_sync(0xffffffffu, w3, j);
            float uq = (hsel < 2) ? (hsel == 0 ? u0 : u1) : (hsel == 2 ? u2 : u3);
            float4 v = *(const float4*)&h[(size_t)sj * 128 + lane * 4];
            acc.x += uq * v.x;
            acc.y += uq * v.y;
            acc.z += uq * v.z;
            acc.w += uq * v.w;
        }
    }
#pragma unroll
    for (int off = 16; off > 0; off >>= 1) {
        d0 += __shfl_xor_sync(0xffffffffu, d0, off);
        d1 += __shfl_xor_sync(0xffffffffu, d1, off);
        d2 += __shfl_xor_sync(0xffffffffu, d2, off);
        d3 += __shfl_xor_sync(0xffffffffu, d3, off);
    }
    float dsel = (hsel < 2) ? (hsel == 0 ? d0 : d1) : (hsel == 2 ? d2 : d3);
    float r = 1.f / (dsel + EPSV);
    float4 bv = *(const float4*)&b[lane * 4];
    float4 o;
    o.x = sigm(acc.x * r + bv.x);
    o.y = sigm(acc.y * r + bv.y);
    o.z = sigm(acc.z * r + bv.z);
    o.w = sigm(acc.w * r + bv.w);
    *(float4*)&out[(size_t)n * 128 + lane * 4] = o;
}

// ---------------- layer-2 aggregation: lane-owns-float2, 4x unrolled ----------------
__global__ void k_agg2(const float* __restrict__ h, const float* __restrict__ b,
                       float* __restrict__ out) {
    int n = (blockIdx.x * blockDim.x + threadIdx.x) >> 5;
    int lane = threadIdx.x & 31;
    if (n >= NN) return;
    int beg = g_off[n], end = g_off[n + 1];
    float ad = g_ad2[n];

    float2 acc = make_float2(0.f, 0.f);
    float d = 0.f;
    for (int e0 = beg; e0 < end; e0 += 32) {
        int cnt = min(32, end - e0);
        int s = 0;
        float w = 0.f;
        if (lane < cnt) {
            s = g_csr[e0 + lane];
            w = __expf(lrelu(g_as2[s] + ad));
            d += w;
        }
        int j = 0;
        for (; j + 4 <= cnt; j += 4) {
            int sj[4];
            float u[4];
            float2 v[4];
#pragma unroll
            for (int q = 0; q < 4; q++) {
                sj[q] = __shfl_sync(0xffffffffu, s, j + q);
                u[q] = __shfl_sync(0xffffffffu, w, j + q);
            }
#pragma unroll
            for (int q = 0; q < 4; q++)
                v[q] = *(const float2*)&h[(size_t)sj[q] * 64 + lane * 2];
#pragma unroll
            for (int q = 0; q < 4; q++) {
                acc.x += u[q] * v[q].x;
                acc.y += u[q] * v[q].y;
            }
        }
        for (; j < cnt; j++) {
            int sj = __shfl_sync(0xffffffffu, s, j);
            float u = __shfl_sync(0xffffffffu, w, j);
            float2 v = *(const float2*)&h[(size_t)sj * 64 + lane * 2];
            acc.x += u * v.x;
            acc.y += u * v.y;
        }
    }
#pragma unroll
    for (int off = 16; off > 0; off >>= 1)
        d += __shfl_xor_sync(0xffffffffu, d, off);
    float r = 1.f / (d + EPSV);
    float2 bv = *(const float2*)&b[lane * 2];
    float2 o;
    o.x = sigm(acc.x * r + bv.x);
    o.y = sigm(acc.y * r + bv.y);
    *(float2*)&out[(size_t)n * 64 + lane * 2] = o;
}

// ---------------- launch ----------------
extern "C" void kernel_launch(void* const* d_in, const int* in_sizes, int n_in,
                              void* d_out, int out_size) {
    const float* x     = (const float*)d_in[0];
    const void*  ei    = d_in[1];
    const float* W1    = (const float*)d_in[2];
    const float* at_s1 = (const float*)d_in[3];
    const float* at_d1 = (const float*)d_in[4];
    const float* b1    = (const float*)d_in[5];
    const float* W2    = (const float*)d_in[6];
    const float* at_s2 = (const float*)d_in[7];
    const float* at_d2 = (const float*)d_in[8];
    const float* b2    = (const float*)d_in[9];
    float* out = (float*)d_out;

    float *h1p, *out1p, *h2p, *as1p, *ad1p, *as2p, *ad2p;
    cudaGetSymbolAddress((void**)&h1p, g_h1);
    cudaGetSymbolAddress((void**)&out1p, g_out1);
    cudaGetSymbolAddress((void**)&h2p, g_h2);
    cudaGetSymbolAddress((void**)&as1p, g_as1);
    cudaGetSymbolAddress((void**)&ad1p, g_ad1);
    cudaGetSymbolAddress((void**)&as2p, g_as2);
    cudaGetSymbolAddress((void**)&ad2p, g_ad2);

    const int SM1 = 4 * 128 * 72 * 2 / 2 * 2 + 2 * 32 * 136 * 4 + 2 * 128 * 4;  // 72704
    const int SM2 = 2 * 128 * 72 * 2 + 2 * 32 * 72 * 4 + 2 * 64 * 4;            // 55808
    cudaFuncSetAttribute(k_mma<128, 4, 32>, cudaFuncAttributeMaxDynamicSharedMemorySize, SM1);
    cudaFuncSetAttribute(k_mma<64, 1, 64>, cudaFuncAttributeMaxDynamicSharedMemorySize, SM2);

    // mma1 kept at launch index 3 for the ncu capture window.
    k_zero_detect<<<256, 256>>>((const unsigned int*)ei);               // 0
    k_convert<<<EE / 1024, 256>>>(ei);                                  // 1
    k_scan<<<1, 1024>>>();                                              // 2
    k_mma<128, 4, 32><<<NN / 128, 256, SM1>>>(x, W1, at_s1, at_d1,      // 3
                                              h1p, as1p, ad1p);
    k_csr<<<EE / 1024, 256>>>();                                        // 4
    k_agg1<<<NN / 8, 256>>>(h1p, b1, out1p);                            // 5

    k_mma<64, 1, 64><<<NN / 128, 256, SM2>>>(out1p, W2, at_s2, at_d2,   // 6
                                             h2p, as2p, ad2p);
    k_agg2<<<NN / 8, 256>>>(h2p, b2, out);                              // 7
}